// round 12
// baseline (speedup 1.0000x reference)
#include <cuda_runtime.h>
#include <cuda_fp16.h>
#include <stdint.h>
#include <math.h>

// Problem constants
#define BB 2
#define TT 2048
#define CC 2048
#define NHH 16
#define HDD 128
#define MTOK (BB*TT)        // 4096
#define THREEC (3*CC)       // 6144

// ---------------- scratch (device globals) ----------------
__device__ float  g_qkv[(size_t)MTOK * THREEC];
__device__ __half g_wha[(size_t)THREEC * CC];
__device__ __half g_whp[(size_t)CC * CC];
__device__ __half g_xh[(size_t)MTOK * CC];
__device__ __half g_qh[(size_t)BB*NHH*TT*HDD];
__device__ __half g_kh[(size_t)BB*NHH*TT*HDD];
__device__ __half g_vh[(size_t)BB*NHH*TT*HDD];
__device__ __half g_yh[(size_t)MTOK * CC];

// ===================== helpers =====================
__device__ __forceinline__ uint32_t smem_u32(const void* p) {
    uint32_t a;
    asm("{ .reg .u64 t; cvta.to.shared.u64 t, %1; cvt.u32.u64 %0, t; }" : "=r"(a) : "l"(p));
    return a;
}
#define CP_ASYNC16(s, g) asm volatile("cp.async.cg.shared.global [%0], [%1], 16;" :: "r"(s), "l"(g))
#define CP_COMMIT()      asm volatile("cp.async.commit_group;" ::: "memory")
#define CP_WAIT(n)       asm volatile("cp.async.wait_group %0;" :: "n"(n) : "memory")

__device__ __forceinline__ void ldm_x4(uint32_t& r0, uint32_t& r1, uint32_t& r2, uint32_t& r3,
                                       uint32_t addr) {
    asm volatile("ldmatrix.sync.aligned.m8n8.x4.shared.b16 {%0,%1,%2,%3}, [%4];"
                 : "=r"(r0), "=r"(r1), "=r"(r2), "=r"(r3) : "r"(addr));
}
__device__ __forceinline__ void ldm_x4_t(uint32_t& r0, uint32_t& r1, uint32_t& r2, uint32_t& r3,
                                         uint32_t addr) {
    asm volatile("ldmatrix.sync.aligned.m8n8.x4.trans.shared.b16 {%0,%1,%2,%3}, [%4];"
                 : "=r"(r0), "=r"(r1), "=r"(r2), "=r"(r3) : "r"(addr));
}
__device__ __forceinline__ void mma_f16(float* c, const uint32_t* a, uint32_t b0, uint32_t b1) {
    asm volatile(
        "mma.sync.aligned.m16n8k16.row.col.f32.f16.f16.f32 "
        "{%0,%1,%2,%3}, {%4,%5,%6,%7}, {%8,%9}, {%0,%1,%2,%3};"
        : "+f"(c[0]), "+f"(c[1]), "+f"(c[2]), "+f"(c[3])
        : "r"(a[0]), "r"(a[1]), "r"(a[2]), "r"(a[3]), "r"(b0), "r"(b1));
}
__device__ __forceinline__ uint32_t ex2_f16x2(uint32_t z) {
    uint32_t r;
    asm volatile("ex2.approx.f16x2 %0, %1;" : "=r"(r) : "r"(z));
    return r;
}

// ===================== fp16 HMMA weight GEMM =====================
// out[m,n] = scales[n] * sum_k A[m,k] * W[n,k]
// 128x128 tile, 128 threads, 4 warps of 64x64. 4-stage cp.async, K chunk 32.
#define BM 128
#define BN 128
#define PKH 40                        // halves pitch
#define STG_H (BM * PKH)              // 5120 halves
#define NSTG 4
#define GEMM_SMEM (NSTG * STG_H * 2 * 2)   // 81920 bytes

__global__ __launch_bounds__(128) void gemm_mma_f16(
    const __half* __restrict__ A, const __half* __restrict__ Wb,
    const float* __restrict__ scales, float* __restrict__ out, int Ndim, int Kdim)
{
    extern __shared__ __half smg[];
    const uint32_t sbA = smem_u32(smg);
    const uint32_t sbB = sbA + NSTG * STG_H * 2;

    const int tid = threadIdx.x, lane = tid & 31, wid = tid >> 5;
    const int wm = (wid >> 1) * 64;
    const int wn = (wid & 1) * 64;
    const int m0 = blockIdx.y * BM;
    const int n0 = blockIdx.x * BN;
    const int KC = Kdim >> 5;

    float c[4][8][4];
#pragma unroll
    for (int i = 0; i < 4; i++)
#pragma unroll
        for (int j = 0; j < 8; j++)
#pragma unroll
            for (int q = 0; q < 4; q++) c[i][j][q] = 0.0f;

    auto load_stage = [&](int kc, int s) {
        const int k0 = kc << 5;
        const __half* ga = A + (size_t)(m0 + tid) * Kdim + k0;
        const __half* gb = Wb + (size_t)(n0 + tid) * Kdim + k0;
        uint32_t sa = sbA + (uint32_t)(s * STG_H + tid * PKH) * 2;
        uint32_t sbq = sbB + (uint32_t)(s * STG_H + tid * PKH) * 2;
#pragma unroll
        for (int q = 0; q < 4; q++) {
            CP_ASYNC16(sa + q * 16, ga + q * 8);
            CP_ASYNC16(sbq + q * 16, gb + q * 8);
        }
    };

#pragma unroll
    for (int s = 0; s < NSTG - 1; s++) { load_stage(s, s); CP_COMMIT(); }

    for (int kc = 0; kc < KC; kc++) {
        const int s = kc % NSTG;
        CP_WAIT(NSTG - 2);
        __syncthreads();
        const int kl = kc + NSTG - 1;
        if (kl < KC) load_stage(kl, kl % NSTG);
        CP_COMMIT();

#pragma unroll
        for (int ks = 0; ks < 2; ks++) {
            uint32_t a[4][4];
#pragma unroll
            for (int mi = 0; mi < 4; mi++) {
                int row = wm + mi * 16 + (lane & 15);
                int col = ks * 16 + (lane >> 4) * 8;
                ldm_x4(a[mi][0], a[mi][1], a[mi][2], a[mi][3],
                       sbA + (uint32_t)(s * STG_H + row * PKH + col) * 2);
            }
            uint32_t b[8][2];
#pragma unroll
            for (int ni = 0; ni < 4; ni++) {
                int row = wn + ni * 16 + (lane & 7) + ((lane >> 4) << 3);
                int col = ks * 16 + ((lane >> 3) & 1) * 8;
                uint32_t r0, r1, r2, r3;
                ldm_x4(r0, r1, r2, r3, sbB + (uint32_t)(s * STG_H + row * PKH + col) * 2);
                b[ni * 2 + 0][0] = r0; b[ni * 2 + 0][1] = r1;
                b[ni * 2 + 1][0] = r2; b[ni * 2 + 1][1] = r3;
            }
#pragma unroll
            for (int mi = 0; mi < 4; mi++)
#pragma unroll
                for (int nj = 0; nj < 8; nj++)
                    mma_f16(c[mi][nj], a[mi], b[nj][0], b[nj][1]);
        }
    }

    const int gr = lane >> 2;
    const int gc = (lane & 3) * 2;
#pragma unroll
    for (int mi = 0; mi < 4; mi++) {
#pragma unroll
        for (int nj = 0; nj < 8; nj++) {
            int m = m0 + wm + mi * 16 + gr;
            int n = n0 + wn + nj * 8 + gc;
            float s0 = __ldg(&scales[n]);
            float s1 = __ldg(&scales[n + 1]);
            float2 v0 = {c[mi][nj][0] * s0, c[mi][nj][1] * s1};
            float2 v1 = {c[mi][nj][2] * s0, c[mi][nj][3] * s1};
            *(float2*)&out[(size_t)m * Ndim + n] = v0;
            *(float2*)&out[(size_t)(m + 8) * Ndim + n] = v1;
        }
    }
}

// ===================== conversions =====================
__global__ __launch_bounds__(256) void conv_w_kernel(const int* __restrict__ W,
                                                     __half* __restrict__ O, int n4)
{
    int i = blockIdx.x * blockDim.x + threadIdx.x;
    if (i >= n4) return;
    int4 w = ((const int4*)W)[i];
    __half o[4] = { __int2half_rn(w.x), __int2half_rn(w.y),
                    __int2half_rn(w.z), __int2half_rn(w.w) };
    ((uint2*)O)[i] = *(uint2*)o;
}

__global__ __launch_bounds__(256) void conv_x_kernel(const float* __restrict__ X,
                                                     __half* __restrict__ O, int n4)
{
    int i = blockIdx.x * blockDim.x + threadIdx.x;
    if (i >= n4) return;
    float4 v = ((const float4*)X)[i];
    __half o[4] = { __float2half_rn(v.x), __float2half_rn(v.y),
                    __float2half_rn(v.z), __float2half_rn(v.w) };
    ((uint2*)O)[i] = *(uint2*)o;
}

// ===================== split + L2 norm -> fp16 =====================
__global__ __launch_bounds__(256) void split_norm_kernel(
    const float* __restrict__ qkv, const float* __restrict__ gain_p,
    __half* __restrict__ q, __half* __restrict__ k, __half* __restrict__ v)
{
    int gw = (blockIdx.x * blockDim.x + threadIdx.x) >> 5;
    int lane = threadIdx.x & 31;
    int which = gw / (BB * TT * NHH);
    int rem = gw % (BB * TT * NHH);
    int b = rem / (TT * NHH);
    int rem2 = rem % (TT * NHH);
    int t = rem2 / NHH;
    int h = rem2 % NHH;

    const float* src = qkv + (size_t)(b * TT + t) * THREEC + which * CC + h * HDD + lane * 4;
    float4 x = *(const float4*)src;

    if (which != 2) {
        float ss = x.x * x.x + x.y * x.y + x.z * x.z + x.w * x.w;
#pragma unroll
        for (int o = 16; o > 0; o >>= 1) ss += __shfl_xor_sync(0xffffffffu, ss, o);
        float n = sqrtf(ss);
        float s = gain_p[0] / fmaxf(n, 1e-12f);
        x.x *= s; x.y *= s; x.z *= s; x.w *= s;
    }

    __half* dst = (which == 0) ? q : (which == 1) ? k : v;
    size_t base = ((size_t)(b * NHH + h) * TT + t) * HDD + lane * 4;
    __half o[4] = { __float2half_rn(x.x), __float2half_rn(x.y),
                    __float2half_rn(x.z), __float2half_rn(x.w) };
    *(uint2*)&dst[base] = *(uint2*)o;
}

// ===================== fp16 HMMA flash attention =====================
#define FPH 136
#define FQ 0
#define FK (64*FPH)
#define FV (2*64*FPH)
#define FLASH_SMEM (3*64*FPH*2)    // 52224 bytes

__global__ __launch_bounds__(128) void flash_mma_kernel(
    const __half* __restrict__ Qg, const __half* __restrict__ Kg,
    const __half* __restrict__ Vg, __half* __restrict__ Yh)
{
    extern __shared__ __half fsm[];
    const uint32_t sb = smem_u32(fsm);
    const int tid = threadIdx.x, lane = tid & 31, wid = tid >> 5;
    const int wr = wid * 16;
    const int qb = gridDim.x - 1 - blockIdx.x;     // heavy blocks first
    const int bh = blockIdx.y;
    const int q0 = qb * 64;
    // logits scaled into log2 domain: z = s * (1/sqrt(128)) * log2(e)
    const float SCLOG2E = 0.08838834764831845f * 1.4426950408889634f;

    const size_t bhoff = (size_t)bh * TT * HDD;
    const __half* Qb = Qg + bhoff;
    const __half* Kb = Kg + bhoff;
    const __half* Vb = Vg + bhoff;

    {
        const int row = tid >> 1;
        const int c = (tid & 1) * 64;
#pragma unroll
        for (int q8 = 0; q8 < 64; q8 += 8) {
            uint4 qv = *(const uint4*)(Qb + (size_t)(q0 + row) * HDD + c + q8);
            uint32_t so = (row * FPH + c + q8) * 2;
            *(uint2*)((char*)fsm + FQ * 2 + so)     = make_uint2(qv.x, qv.y);
            *(uint2*)((char*)fsm + FQ * 2 + so + 8) = make_uint2(qv.z, qv.w);
        }
    }

    float o[16][4];
#pragma unroll
    for (int i = 0; i < 16; i++)
#pragma unroll
        for (int j = 0; j < 4; j++) o[i][j] = 0.0f;
    float m0v = -1e30f, m1v = -1e30f, l0 = 0.0f, l1 = 0.0f;

    for (int jb = 0; jb <= qb; jb++) {
        const int k0 = jb * 64;
        __syncthreads();
        {
            const int row = tid >> 1;
            const int c = (tid & 1) * 64;
#pragma unroll
            for (int q8 = 0; q8 < 64; q8 += 8) {
                uint32_t so = (row * FPH + c + q8) * 2;
                uint4 a0 = *(const uint4*)(Kb + (size_t)(k0 + row) * HDD + c + q8);
                *(uint2*)((char*)fsm + FK * 2 + so)     = make_uint2(a0.x, a0.y);
                *(uint2*)((char*)fsm + FK * 2 + so + 8) = make_uint2(a0.z, a0.w);
                uint4 a2 = *(const uint4*)(Vb + (size_t)(k0 + row) * HDD + c + q8);
                *(uint2*)((char*)fsm + FV * 2 + so)     = make_uint2(a2.x, a2.y);
                *(uint2*)((char*)fsm + FV * 2 + so + 8) = make_uint2(a2.z, a2.w);
            }
        }
        __syncthreads();

        float s[8][4];
#pragma unroll
        for (int i = 0; i < 8; i++)
#pragma unroll
            for (int j = 0; j < 4; j++) s[i][j] = 0.0f;

#pragma unroll
        for (int ks = 0; ks < 8; ks++) {
            uint32_t a[4];
            uint32_t qoff = sb + (uint32_t)((wr + (lane & 15)) * FPH + ks * 16 + (lane >> 4) * 8) * 2;
            ldm_x4(a[0], a[1], a[2], a[3], qoff + FQ * 2);
#pragma unroll
            for (int nt2 = 0; nt2 < 4; nt2++) {
                uint32_t koff = sb + (uint32_t)((nt2 * 16 + (lane & 7) + ((lane >> 4) << 3)) * FPH
                                                + ks * 16 + ((lane >> 3) & 1) * 8) * 2;
                uint32_t b0, b1, b2, b3;
                ldm_x4(b0, b1, b2, b3, koff + FK * 2);
                mma_f16(s[nt2 * 2 + 0], a, b0, b1);
                mma_f16(s[nt2 * 2 + 1], a, b2, b3);
            }
        }

        // scale (log2 domain) + causal mask
        const int lr0 = wr + (lane >> 2);
        const int lc0 = (lane & 3) * 2;
#pragma unroll
        for (int nt = 0; nt < 8; nt++) {
#pragma unroll
            for (int j = 0; j < 4; j++) s[nt][j] *= SCLOG2E;
            if (jb == qb) {
                int col = nt * 8 + lc0;
                if (col > lr0)     s[nt][0] = -1e30f;
                if (col + 1 > lr0) s[nt][1] = -1e30f;
                if (col > lr0 + 8)     s[nt][2] = -1e30f;
                if (col + 1 > lr0 + 8) s[nt][3] = -1e30f;
            }
        }

        // online softmax (base-2, fp16x2 ex2)
        float rm0 = -1e30f, rm1 = -1e30f;
#pragma unroll
        for (int nt = 0; nt < 8; nt++) {
            rm0 = fmaxf(rm0, fmaxf(s[nt][0], s[nt][1]));
            rm1 = fmaxf(rm1, fmaxf(s[nt][2], s[nt][3]));
        }
        rm0 = fmaxf(rm0, __shfl_xor_sync(0xffffffffu, rm0, 1));
        rm0 = fmaxf(rm0, __shfl_xor_sync(0xffffffffu, rm0, 2));
        rm1 = fmaxf(rm1, __shfl_xor_sync(0xffffffffu, rm1, 1));
        rm1 = fmaxf(rm1, __shfl_xor_sync(0xffffffffu, rm1, 2));
        float mn0 = fmaxf(m0v, rm0), mn1 = fmaxf(m1v, rm1);
        float cor0 = exp2f(m0v - mn0), cor1 = exp2f(m1v - mn1);
        float sum0 = 0.0f, sum1 = 0.0f;
        uint32_t pf[4][4];
#pragma unroll
        for (int nt = 0; nt < 8; nt++) {
            __half2 z01 = __floats2half2_rn(s[nt][0] - mn0, s[nt][1] - mn0);
            __half2 z23 = __floats2half2_rn(s[nt][2] - mn1, s[nt][3] - mn1);
            uint32_t p01 = ex2_f16x2(*(uint32_t*)&z01);
            uint32_t p23 = ex2_f16x2(*(uint32_t*)&z23);
            float2 f01 = __half22float2(*(__half2*)&p01);
            float2 f23 = __half22float2(*(__half2*)&p23);
            sum0 += f01.x + f01.y;
            sum1 += f23.x + f23.y;
            int ks = nt >> 1;
            int hi2 = nt & 1;
            pf[ks][hi2 * 2 + 0] = p01;
            pf[ks][hi2 * 2 + 1] = p23;
        }
        sum0 += __shfl_xor_sync(0xffffffffu, sum0, 1);
        sum0 += __shfl_xor_sync(0xffffffffu, sum0, 2);
        sum1 += __shfl_xor_sync(0xffffffffu, sum1, 1);
        sum1 += __shfl_xor_sync(0xffffffffu, sum1, 2);
        l0 = l0 * cor0 + sum0;
        l1 = l1 * cor1 + sum1;
        m0v = mn0; m1v = mn1;
#pragma unroll
        for (int nt = 0; nt < 16; nt++) {
            o[nt][0] *= cor0; o[nt][1] *= cor0;
            o[nt][2] *= cor1; o[nt][3] *= cor1;
        }

        // O += P V
#pragma unroll
        for (int ks = 0; ks < 4; ks++) {
#pragma unroll
            for (int nt2 = 0; nt2 < 8; nt2++) {
                uint32_t voff = sb + FV * 2 +
                    (uint32_t)((ks * 16 + (lane & 15)) * FPH + nt2 * 16 + (lane >> 4) * 8) * 2;
                uint32_t b0, b1, b2, b3;
                ldm_x4_t(b0, b1, b2, b3, voff);
                mma_f16(o[nt2 * 2 + 0], pf[ks], b0, b1);
                mma_f16(o[nt2 * 2 + 1], pf[ks], b2, b3);
            }
        }
    }

    // epilogue
    const int b = bh / NHH, h = bh % NHH;
    const int r0 = wr + (lane >> 2);
    const int cbase = (lane & 3) * 2;
    float inv0 = 1.0f / l0, inv1 = 1.0f / l1;
    size_t rowA = (size_t)(b * TT + q0 + r0) * CC + h * HDD;
    size_t rowB = (size_t)(b * TT + q0 + r0 + 8) * CC + h * HDD;
#pragma unroll
    for (int nt = 0; nt < 16; nt++) {
        int col = nt * 8 + cbase;
        __half2 vA = {__float2half_rn(o[nt][0] * inv0), __float2half_rn(o[nt][1] * inv0)};
        __half2 vB = {__float2half_rn(o[nt][2] * inv1), __float2half_rn(o[nt][3] * inv1)};
        *(uint32_t*)&Yh[rowA + col] = *(uint32_t*)&vA;
        *(uint32_t*)&Yh[rowB + col] = *(uint32_t*)&vB;
    }
}

// ===================== launch =====================
extern "C" void kernel_launch(void* const* d_in, const int* in_sizes, int n_in,
                              void* d_out, int out_size)
{
    const float* x           = (const float*)d_in[0];
    const int*   attn_w      = (const int*)d_in[1];
    const float* attn_scales = (const float*)d_in[2];
    const int*   proj_w      = (const int*)d_in[3];
    const float* proj_scales = (const float*)d_in[4];
    const float* qk_gain     = (const float*)d_in[5];
    float* out = (float*)d_out;

    float* p_qkv;
    __half *p_wha, *p_whp, *p_xh, *p_qh, *p_kh, *p_vh, *p_yh;
    cudaGetSymbolAddress((void**)&p_qkv, g_qkv);
    cudaGetSymbolAddress((void**)&p_wha, g_wha);
    cudaGetSymbolAddress((void**)&p_whp, g_whp);
    cudaGetSymbolAddress((void**)&p_xh,  g_xh);
    cudaGetSymbolAddress((void**)&p_qh,  g_qh);
    cudaGetSymbolAddress((void**)&p_kh,  g_kh);
    cudaGetSymbolAddress((void**)&p_vh,  g_vh);
    cudaGetSymbolAddress((void**)&p_yh,  g_yh);

    cudaFuncSetAttribute(gemm_mma_f16, cudaFuncAttributeMaxDynamicSharedMemorySize, GEMM_SMEM);
    cudaFuncSetAttribute(flash_mma_kernel, cudaFuncAttributeMaxDynamicSharedMemorySize, FLASH_SMEM);

    // 0) weight conversions (int32 -> fp16, exact)
    conv_w_kernel<<<(THREEC * CC / 4 + 255) / 256, 256>>>(attn_w, p_wha, THREEC * CC / 4);
    conv_w_kernel<<<(CC * CC / 4 + 255) / 256, 256>>>(proj_w, p_whp, CC * CC / 4);

    // 1) x -> fp16
    conv_x_kernel<<<(MTOK * CC / 4 + 255) / 256, 256>>>(x, p_xh, MTOK * CC / 4);

    // 2) QKV = x @ Wa^T
    gemm_mma_f16<<<dim3(THREEC / BN, MTOK / BM), 128, GEMM_SMEM>>>(
        p_xh, p_wha, attn_scales, p_qkv, THREEC, CC);

    // 3) split + L2 norm -> fp16 q/k/v
    split_norm_kernel<<<3 * BB * TT * NHH / 8, 256>>>(p_qkv, qk_gain, p_qh, p_kh, p_vh);

    // 4) fp16 HMMA flash attention -> yh
    flash_mma_kernel<<<dim3(TT / 64, BB * NHH), 128, FLASH_SMEM>>>(p_qh, p_kh, p_vh, p_yh);

    // 5) out = y @ Wp^T
    gemm_mma_f16<<<dim3(CC / BN, MTOK / BM), 128, GEMM_SMEM>>>(
        p_yh, p_whp, proj_scales, out, CC, CC);
}

// round 14
// speedup vs baseline: 1.2115x; 1.2115x over previous
#include <cuda_runtime.h>
#include <cuda_fp16.h>
#include <stdint.h>
#include <math.h>

// Problem constants
#define BB 2
#define TT 2048
#define CC 2048
#define NHH 16
#define HDD 128
#define MTOK (BB*TT)        // 4096
#define THREEC (3*CC)       // 6144

// ---------------- scratch (device globals) ----------------
__device__ float  g_qkv[(size_t)MTOK * THREEC];
__device__ __half g_wha[(size_t)THREEC * CC];
__device__ __half g_whp[(size_t)CC * CC];
__device__ __half g_xh[(size_t)MTOK * CC];
__device__ __half g_qh[(size_t)BB*NHH*TT*HDD];
__device__ __half g_kh[(size_t)BB*NHH*TT*HDD];
__device__ __half g_vh[(size_t)BB*NHH*TT*HDD];
__device__ __half g_yh[(size_t)MTOK * CC];

// ===================== helpers =====================
__device__ __forceinline__ uint32_t smem_u32(const void* p) {
    uint32_t a;
    asm("{ .reg .u64 t; cvta.to.shared.u64 t, %1; cvt.u32.u64 %0, t; }" : "=r"(a) : "l"(p));
    return a;
}
#define CP_ASYNC16(s, g) asm volatile("cp.async.cg.shared.global [%0], [%1], 16;" :: "r"(s), "l"(g))
#define CP_COMMIT()      asm volatile("cp.async.commit_group;" ::: "memory")
#define CP_WAIT(n)       asm volatile("cp.async.wait_group %0;" :: "n"(n) : "memory")

__device__ __forceinline__ void ldm_x4(uint32_t& r0, uint32_t& r1, uint32_t& r2, uint32_t& r3,
                                       uint32_t addr) {
    asm volatile("ldmatrix.sync.aligned.m8n8.x4.shared.b16 {%0,%1,%2,%3}, [%4];"
                 : "=r"(r0), "=r"(r1), "=r"(r2), "=r"(r3) : "r"(addr));
}
__device__ __forceinline__ void ldm_x4_t(uint32_t& r0, uint32_t& r1, uint32_t& r2, uint32_t& r3,
                                         uint32_t addr) {
    asm volatile("ldmatrix.sync.aligned.m8n8.x4.trans.shared.b16 {%0,%1,%2,%3}, [%4];"
                 : "=r"(r0), "=r"(r1), "=r"(r2), "=r"(r3) : "r"(addr));
}
__device__ __forceinline__ void mma_f16(float* c, const uint32_t* a, uint32_t b0, uint32_t b1) {
    asm volatile(
        "mma.sync.aligned.m16n8k16.row.col.f32.f16.f16.f32 "
        "{%0,%1,%2,%3}, {%4,%5,%6,%7}, {%8,%9}, {%0,%1,%2,%3};"
        : "+f"(c[0]), "+f"(c[1]), "+f"(c[2]), "+f"(c[3])
        : "r"(a[0]), "r"(a[1]), "r"(a[2]), "r"(a[3]), "r"(b0), "r"(b1));
}
__device__ __forceinline__ uint32_t ex2_f16x2(uint32_t z) {
    uint32_t r;
    asm volatile("ex2.approx.f16x2 %0, %1;" : "=r"(r) : "r"(z));
    return r;
}

// ===================== fp16 HMMA weight GEMM (R7 proven config) =====================
// out[m,n] = scales[n] * sum_k A[m,k] * W[n,k]
// 128x128 tile, 256 threads, 8 warps (2x4), warp tile 64x32, 4-stage cp.async.
#define BM 128
#define BN 128
#define PKH 40                        // halves pitch
#define STG_H (BM * PKH)              // 5120 halves
#define NSTG 4
#define GEMM_SMEM (NSTG * STG_H * 2 * 2)   // 81920 bytes

__global__ __launch_bounds__(256) void gemm_mma_f16(
    const __half* __restrict__ A, const __half* __restrict__ Wb,
    const float* __restrict__ scales, float* __restrict__ out, int Ndim, int Kdim)
{
    extern __shared__ __half smg[];
    const uint32_t sbA = smem_u32(smg);
    const uint32_t sbB = sbA + NSTG * STG_H * 2;

    const int tid = threadIdx.x, lane = tid & 31, wid = tid >> 5;
    const int wm = (wid >> 2) * 64;
    const int wn = (wid & 3) * 32;
    const int m0 = blockIdx.y * BM;
    const int n0 = blockIdx.x * BN;
    const int KC = Kdim >> 5;

    float c[4][4][4];
#pragma unroll
    for (int i = 0; i < 4; i++)
#pragma unroll
        for (int j = 0; j < 4; j++)
#pragma unroll
            for (int q = 0; q < 4; q++) c[i][j][q] = 0.0f;

    const int lr = tid >> 2;
    const int lq = (tid & 3) * 8;

    auto load_stage = [&](int kc, int s) {
        const int k0 = kc << 5;
#pragma unroll
        for (int half = 0; half < 2; half++) {
            int r = lr + half * 64;
            CP_ASYNC16(sbA + (uint32_t)(s * STG_H + r * PKH + lq) * 2,
                       A + (size_t)(m0 + r) * Kdim + k0 + lq);
            CP_ASYNC16(sbB + (uint32_t)(s * STG_H + r * PKH + lq) * 2,
                       Wb + (size_t)(n0 + r) * Kdim + k0 + lq);
        }
    };

#pragma unroll
    for (int s = 0; s < NSTG - 1; s++) { load_stage(s, s); CP_COMMIT(); }

    for (int kc = 0; kc < KC; kc++) {
        const int s = kc % NSTG;
        CP_WAIT(NSTG - 2);
        __syncthreads();
        const int kl = kc + NSTG - 1;
        if (kl < KC) load_stage(kl, kl % NSTG);
        CP_COMMIT();

#pragma unroll
        for (int ks = 0; ks < 2; ks++) {
            uint32_t a[4][4];
#pragma unroll
            for (int mi = 0; mi < 4; mi++) {
                int row = wm + mi * 16 + (lane & 15);
                int col = ks * 16 + (lane >> 4) * 8;
                ldm_x4(a[mi][0], a[mi][1], a[mi][2], a[mi][3],
                       sbA + (uint32_t)(s * STG_H + row * PKH + col) * 2);
            }
            uint32_t b[4][2];
#pragma unroll
            for (int ni = 0; ni < 2; ni++) {
                int row = wn + ni * 16 + (lane & 7) + ((lane >> 4) << 3);
                int col = ks * 16 + ((lane >> 3) & 1) * 8;
                uint32_t r0, r1, r2, r3;
                ldm_x4(r0, r1, r2, r3, sbB + (uint32_t)(s * STG_H + row * PKH + col) * 2);
                b[ni * 2 + 0][0] = r0; b[ni * 2 + 0][1] = r1;
                b[ni * 2 + 1][0] = r2; b[ni * 2 + 1][1] = r3;
            }
#pragma unroll
            for (int mi = 0; mi < 4; mi++)
#pragma unroll
                for (int nj = 0; nj < 4; nj++)
                    mma_f16(c[mi][nj], a[mi], b[nj][0], b[nj][1]);
        }
    }

    const int gr = lane >> 2;
    const int gc = (lane & 3) * 2;
#pragma unroll
    for (int mi = 0; mi < 4; mi++) {
#pragma unroll
        for (int nj = 0; nj < 4; nj++) {
            int m = m0 + wm + mi * 16 + gr;
            int n = n0 + wn + nj * 8 + gc;
            float s0 = __ldg(&scales[n]);
            float s1 = __ldg(&scales[n + 1]);
            float2 v0 = {c[mi][nj][0] * s0, c[mi][nj][1] * s1};
            float2 v1 = {c[mi][nj][2] * s0, c[mi][nj][3] * s1};
            *(float2*)&out[(size_t)m * Ndim + n] = v0;
            *(float2*)&out[(size_t)(m + 8) * Ndim + n] = v1;
        }
    }
}

// ===================== conversions =====================
__global__ __launch_bounds__(256) void conv_w_kernel(const int* __restrict__ W,
                                                     __half* __restrict__ O, int n4)
{
    int i = blockIdx.x * blockDim.x + threadIdx.x;
    if (i >= n4) return;
    int4 w = ((const int4*)W)[i];
    __half o[4] = { __int2half_rn(w.x), __int2half_rn(w.y),
                    __int2half_rn(w.z), __int2half_rn(w.w) };
    ((uint2*)O)[i] = *(uint2*)o;
}

__global__ __launch_bounds__(256) void conv_x_kernel(const float* __restrict__ X,
                                                     __half* __restrict__ O, int n4)
{
    int i = blockIdx.x * blockDim.x + threadIdx.x;
    if (i >= n4) return;
    float4 v = ((const float4*)X)[i];
    __half o[4] = { __float2half_rn(v.x), __float2half_rn(v.y),
                    __float2half_rn(v.z), __float2half_rn(v.w) };
    ((uint2*)O)[i] = *(uint2*)o;
}

// ===================== split + L2 norm -> fp16 =====================
__global__ __launch_bounds__(256) void split_norm_kernel(
    const float* __restrict__ qkv, const float* __restrict__ gain_p,
    __half* __restrict__ q, __half* __restrict__ k, __half* __restrict__ v)
{
    int gw = (blockIdx.x * blockDim.x + threadIdx.x) >> 5;
    int lane = threadIdx.x & 31;
    int which = gw / (BB * TT * NHH);
    int rem = gw % (BB * TT * NHH);
    int b = rem / (TT * NHH);
    int rem2 = rem % (TT * NHH);
    int t = rem2 / NHH;
    int h = rem2 % NHH;

    const float* src = qkv + (size_t)(b * TT + t) * THREEC + which * CC + h * HDD + lane * 4;
    float4 x = *(const float4*)src;

    if (which != 2) {
        float ss = x.x * x.x + x.y * x.y + x.z * x.z + x.w * x.w;
#pragma unroll
        for (int o = 16; o > 0; o >>= 1) ss += __shfl_xor_sync(0xffffffffu, ss, o);
        float n = sqrtf(ss);
        float s = gain_p[0] / fmaxf(n, 1e-12f);
        x.x *= s; x.y *= s; x.z *= s; x.w *= s;
    }

    __half* dst = (which == 0) ? q : (which == 1) ? k : v;
    size_t base = ((size_t)(b * NHH + h) * TT + t) * HDD + lane * 4;
    __half o[4] = { __float2half_rn(x.x), __float2half_rn(x.y),
                    __float2half_rn(x.z), __float2half_rn(x.w) };
    *(uint2*)&dst[base] = *(uint2*)o;
}

// ===================== fp16 HMMA flash attention (ex2 softmax) =====================
#define FPH 136
#define FQ 0
#define FK (64*FPH)
#define FV (2*64*FPH)
#define FLASH_SMEM (3*64*FPH*2)    // 52224 bytes

__global__ __launch_bounds__(128) void flash_mma_kernel(
    const __half* __restrict__ Qg, const __half* __restrict__ Kg,
    const __half* __restrict__ Vg, __half* __restrict__ Yh)
{
    extern __shared__ __half fsm[];
    const uint32_t sb = smem_u32(fsm);
    const int tid = threadIdx.x, lane = tid & 31, wid = tid >> 5;
    const int wr = wid * 16;
    const int qb = gridDim.x - 1 - blockIdx.x;     // heavy blocks first
    const int bh = blockIdx.y;
    const int q0 = qb * 64;
    const float SCLOG2E = 0.08838834764831845f * 1.4426950408889634f;

    const size_t bhoff = (size_t)bh * TT * HDD;
    const __half* Qb = Qg + bhoff;
    const __half* Kb = Kg + bhoff;
    const __half* Vb = Vg + bhoff;

    {
        const int row = tid >> 1;
        const int c = (tid & 1) * 64;
#pragma unroll
        for (int q8 = 0; q8 < 64; q8 += 8) {
            uint4 qv = *(const uint4*)(Qb + (size_t)(q0 + row) * HDD + c + q8);
            uint32_t so = (row * FPH + c + q8) * 2;
            *(uint2*)((char*)fsm + FQ * 2 + so)     = make_uint2(qv.x, qv.y);
            *(uint2*)((char*)fsm + FQ * 2 + so + 8) = make_uint2(qv.z, qv.w);
        }
    }

    float o[16][4];
#pragma unroll
    for (int i = 0; i < 16; i++)
#pragma unroll
        for (int j = 0; j < 4; j++) o[i][j] = 0.0f;
    float m0v = -1e30f, m1v = -1e30f, l0 = 0.0f, l1 = 0.0f;

    for (int jb = 0; jb <= qb; jb++) {
        const int k0 = jb * 64;
        __syncthreads();
        {
            const int row = tid >> 1;
            const int c = (tid & 1) * 64;
#pragma unroll
            for (int q8 = 0; q8 < 64; q8 += 8) {
                uint32_t so = (row * FPH + c + q8) * 2;
                uint4 a0 = *(const uint4*)(Kb + (size_t)(k0 + row) * HDD + c + q8);
                *(uint2*)((char*)fsm + FK * 2 + so)     = make_uint2(a0.x, a0.y);
                *(uint2*)((char*)fsm + FK * 2 + so + 8) = make_uint2(a0.z, a0.w);
                uint4 a2 = *(const uint4*)(Vb + (size_t)(k0 + row) * HDD + c + q8);
                *(uint2*)((char*)fsm + FV * 2 + so)     = make_uint2(a2.x, a2.y);
                *(uint2*)((char*)fsm + FV * 2 + so + 8) = make_uint2(a2.z, a2.w);
            }
        }
        __syncthreads();

        float s[8][4];
#pragma unroll
        for (int i = 0; i < 8; i++)
#pragma unroll
            for (int j = 0; j < 4; j++) s[i][j] = 0.0f;

#pragma unroll
        for (int ks = 0; ks < 8; ks++) {
            uint32_t a[4];
            uint32_t qoff = sb + (uint32_t)((wr + (lane & 15)) * FPH + ks * 16 + (lane >> 4) * 8) * 2;
            ldm_x4(a[0], a[1], a[2], a[3], qoff + FQ * 2);
#pragma unroll
            for (int nt2 = 0; nt2 < 4; nt2++) {
                uint32_t koff = sb + (uint32_t)((nt2 * 16 + (lane & 7) + ((lane >> 4) << 3)) * FPH
                                                + ks * 16 + ((lane >> 3) & 1) * 8) * 2;
                uint32_t b0, b1, b2, b3;
                ldm_x4(b0, b1, b2, b3, koff + FK * 2);
                mma_f16(s[nt2 * 2 + 0], a, b0, b1);
                mma_f16(s[nt2 * 2 + 1], a, b2, b3);
            }
        }

        const int lr0 = wr + (lane >> 2);
        const int lc0 = (lane & 3) * 2;
#pragma unroll
        for (int nt = 0; nt < 8; nt++) {
#pragma unroll
            for (int j = 0; j < 4; j++) s[nt][j] *= SCLOG2E;
            if (jb == qb) {
                int col = nt * 8 + lc0;
                if (col > lr0)     s[nt][0] = -1e30f;
                if (col + 1 > lr0) s[nt][1] = -1e30f;
                if (col > lr0 + 8)     s[nt][2] = -1e30f;
                if (col + 1 > lr0 + 8) s[nt][3] = -1e30f;
            }
        }

        float rm0 = -1e30f, rm1 = -1e30f;
#pragma unroll
        for (int nt = 0; nt < 8; nt++) {
            rm0 = fmaxf(rm0, fmaxf(s[nt][0], s[nt][1]));
            rm1 = fmaxf(rm1, fmaxf(s[nt][2], s[nt][3]));
        }
        rm0 = fmaxf(rm0, __shfl_xor_sync(0xffffffffu, rm0, 1));
        rm0 = fmaxf(rm0, __shfl_xor_sync(0xffffffffu, rm0, 2));
        rm1 = fmaxf(rm1, __shfl_xor_sync(0xffffffffu, rm1, 1));
        rm1 = fmaxf(rm1, __shfl_xor_sync(0xffffffffu, rm1, 2));
        float mn0 = fmaxf(m0v, rm0), mn1 = fmaxf(m1v, rm1);
        float cor0 = exp2f(m0v - mn0), cor1 = exp2f(m1v - mn1);
        float sum0 = 0.0f, sum1 = 0.0f;
        uint32_t pf[4][4];
#pragma unroll
        for (int nt = 0; nt < 8; nt++) {
            __half2 z01 = __floats2half2_rn(s[nt][0] - mn0, s[nt][1] - mn0);
            __half2 z23 = __floats2half2_rn(s[nt][2] - mn1, s[nt][3] - mn1);
            uint32_t p01 = ex2_f16x2(*(uint32_t*)&z01);
            uint32_t p23 = ex2_f16x2(*(uint32_t*)&z23);
            float2 f01 = __half22float2(*(__half2*)&p01);
            float2 f23 = __half22float2(*(__half2*)&p23);
            sum0 += f01.x + f01.y;
            sum1 += f23.x + f23.y;
            int ks = nt >> 1;
            int hi2 = nt & 1;
            pf[ks][hi2 * 2 + 0] = p01;
            pf[ks][hi2 * 2 + 1] = p23;
        }
        sum0 += __shfl_xor_sync(0xffffffffu, sum0, 1);
        sum0 += __shfl_xor_sync(0xffffffffu, sum0, 2);
        sum1 += __shfl_xor_sync(0xffffffffu, sum1, 1);
        sum1 += __shfl_xor_sync(0xffffffffu, sum1, 2);
        l0 = l0 * cor0 + sum0;
        l1 = l1 * cor1 + sum1;
        m0v = mn0; m1v = mn1;
#pragma unroll
        for (int nt = 0; nt < 16; nt++) {
            o[nt][0] *= cor0; o[nt][1] *= cor0;
            o[nt][2] *= cor1; o[nt][3] *= cor1;
        }

#pragma unroll
        for (int ks = 0; ks < 4; ks++) {
#pragma unroll
            for (int nt2 = 0; nt2 < 8; nt2++) {
                uint32_t voff = sb + FV * 2 +
                    (uint32_t)((ks * 16 + (lane & 15)) * FPH + nt2 * 16 + (lane >> 4) * 8) * 2;
                uint32_t b0, b1, b2, b3;
                ldm_x4_t(b0, b1, b2, b3, voff);
                mma_f16(o[nt2 * 2 + 0], pf[ks], b0, b1);
                mma_f16(o[nt2 * 2 + 1], pf[ks], b2, b3);
            }
        }
    }

    const int b = bh / NHH, h = bh % NHH;
    const int r0 = wr + (lane >> 2);
    const int cbase = (lane & 3) * 2;
    float inv0 = 1.0f / l0, inv1 = 1.0f / l1;
    size_t rowA = (size_t)(b * TT + q0 + r0) * CC + h * HDD;
    size_t rowB = (size_t)(b * TT + q0 + r0 + 8) * CC + h * HDD;
#pragma unroll
    for (int nt = 0; nt < 16; nt++) {
        int col = nt * 8 + cbase;
        __half2 vA = {__float2half_rn(o[nt][0] * inv0), __float2half_rn(o[nt][1] * inv0)};
        __half2 vB = {__float2half_rn(o[nt][2] * inv1), __float2half_rn(o[nt][3] * inv1)};
        *(uint32_t*)&Yh[rowA + col] = *(uint32_t*)&vA;
        *(uint32_t*)&Yh[rowB + col] = *(uint32_t*)&vB;
    }
}

// ===================== launch =====================
extern "C" void kernel_launch(void* const* d_in, const int* in_sizes, int n_in,
                              void* d_out, int out_size)
{
    const float* x           = (const float*)d_in[0];
    const int*   attn_w      = (const int*)d_in[1];
    const float* attn_scales = (const float*)d_in[2];
    const int*   proj_w      = (const int*)d_in[3];
    const float* proj_scales = (const float*)d_in[4];
    const float* qk_gain     = (const float*)d_in[5];
    float* out = (float*)d_out;

    float* p_qkv;
    __half *p_wha, *p_whp, *p_xh, *p_qh, *p_kh, *p_vh, *p_yh;
    cudaGetSymbolAddress((void**)&p_qkv, g_qkv);
    cudaGetSymbolAddress((void**)&p_wha, g_wha);
    cudaGetSymbolAddress((void**)&p_whp, g_whp);
    cudaGetSymbolAddress((void**)&p_xh,  g_xh);
    cudaGetSymbolAddress((void**)&p_qh,  g_qh);
    cudaGetSymbolAddress((void**)&p_kh,  g_kh);
    cudaGetSymbolAddress((void**)&p_vh,  g_vh);
    cudaGetSymbolAddress((void**)&p_yh,  g_yh);

    cudaFuncSetAttribute(gemm_mma_f16, cudaFuncAttributeMaxDynamicSharedMemorySize, GEMM_SMEM);
    cudaFuncSetAttribute(flash_mma_kernel, cudaFuncAttributeMaxDynamicSharedMemorySize, FLASH_SMEM);

    // 0) weight conversions (int32 -> fp16, exact)
    conv_w_kernel<<<(THREEC * CC / 4 + 255) / 256, 256>>>(attn_w, p_wha, THREEC * CC / 4);
    conv_w_kernel<<<(CC * CC / 4 + 255) / 256, 256>>>(proj_w, p_whp, CC * CC / 4);

    // 1) x -> fp16
    conv_x_kernel<<<(MTOK * CC / 4 + 255) / 256, 256>>>(x, p_xh, MTOK * CC / 4);

    // 2) QKV = x @ Wa^T
    gemm_mma_f16<<<dim3(THREEC / BN, MTOK / BM), 256, GEMM_SMEM>>>(
        p_xh, p_wha, attn_scales, p_qkv, THREEC, CC);

    // 3) split + L2 norm -> fp16 q/k/v
    split_norm_kernel<<<3 * BB * TT * NHH / 8, 256>>>(p_qkv, qk_gain, p_qh, p_kh, p_vh);

    // 4) fp16 HMMA flash attention -> yh
    flash_mma_kernel<<<dim3(TT / 64, BB * NHH), 128, FLASH_SMEM>>>(p_qh, p_kh, p_vh, p_yh);

    // 5) out = y @ Wp^T
    gemm_mma_f16<<<dim3(CC / BN, MTOK / BM), 256, GEMM_SMEM>>>(
        p_yh, p_whp, proj_scales, out, CC, CC);
}

// round 15
// speedup vs baseline: 1.3934x; 1.1501x over previous
#include <cuda_runtime.h>
#include <cuda_fp16.h>
#include <stdint.h>
#include <math.h>

// Problem constants
#define BB 2
#define TT 2048
#define CC 2048
#define NHH 16
#define HDD 128
#define MTOK (BB*TT)        // 4096
#define THREEC (3*CC)       // 6144

// ---------------- scratch (device globals) ----------------
__device__ float  g_qkv[(size_t)MTOK * THREEC];
__device__ __half g_wha[(size_t)THREEC * CC];
__device__ __half g_whp[(size_t)CC * CC];
__device__ __half g_xh[(size_t)MTOK * CC];
__device__ __half g_qh[(size_t)BB*NHH*TT*HDD];
__device__ __half g_kh[(size_t)BB*NHH*TT*HDD];
__device__ __half g_vh[(size_t)BB*NHH*TT*HDD];
__device__ __half g_yh[(size_t)MTOK * CC];

// ===================== helpers =====================
__device__ __forceinline__ uint32_t smem_u32(const void* p) {
    uint32_t a;
    asm("{ .reg .u64 t; cvta.to.shared.u64 t, %1; cvt.u32.u64 %0, t; }" : "=r"(a) : "l"(p));
    return a;
}
#define CP_ASYNC16(s, g) asm volatile("cp.async.cg.shared.global [%0], [%1], 16;" :: "r"(s), "l"(g))
#define CP_COMMIT()      asm volatile("cp.async.commit_group;" ::: "memory")
#define CP_WAIT(n)       asm volatile("cp.async.wait_group %0;" :: "n"(n) : "memory")

__device__ __forceinline__ void ldm_x4(uint32_t& r0, uint32_t& r1, uint32_t& r2, uint32_t& r3,
                                       uint32_t addr) {
    asm volatile("ldmatrix.sync.aligned.m8n8.x4.shared.b16 {%0,%1,%2,%3}, [%4];"
                 : "=r"(r0), "=r"(r1), "=r"(r2), "=r"(r3) : "r"(addr));
}
__device__ __forceinline__ void ldm_x4_t(uint32_t& r0, uint32_t& r1, uint32_t& r2, uint32_t& r3,
                                         uint32_t addr) {
    asm volatile("ldmatrix.sync.aligned.m8n8.x4.trans.shared.b16 {%0,%1,%2,%3}, [%4];"
                 : "=r"(r0), "=r"(r1), "=r"(r2), "=r"(r3) : "r"(addr));
}
__device__ __forceinline__ void mma_f16(float* c, const uint32_t* a, uint32_t b0, uint32_t b1) {
    asm volatile(
        "mma.sync.aligned.m16n8k16.row.col.f32.f16.f16.f32 "
        "{%0,%1,%2,%3}, {%4,%5,%6,%7}, {%8,%9}, {%0,%1,%2,%3};"
        : "+f"(c[0]), "+f"(c[1]), "+f"(c[2]), "+f"(c[3])
        : "r"(a[0]), "r"(a[1]), "r"(a[2]), "r"(a[3]), "r"(b0), "r"(b1));
}
__device__ __forceinline__ uint32_t ex2_f16x2(uint32_t z) {
    uint32_t r;
    asm volatile("ex2.approx.f16x2 %0, %1;" : "=r"(r) : "r"(z));
    return r;
}

// ===================== fp16 HMMA weight GEMM (R7 proven config) =====================
#define BM 128
#define BN 128
#define PKH 40                        // halves pitch
#define STG_H (BM * PKH)              // 5120 halves
#define NSTG 4
#define GEMM_SMEM (NSTG * STG_H * 2 * 2)   // 81920 bytes

__global__ __launch_bounds__(256) void gemm_mma_f16(
    const __half* __restrict__ A, const __half* __restrict__ Wb,
    const float* __restrict__ scales, float* __restrict__ out, int Ndim, int Kdim)
{
    extern __shared__ __half smg[];
    const uint32_t sbA = smem_u32(smg);
    const uint32_t sbB = sbA + NSTG * STG_H * 2;

    const int tid = threadIdx.x, lane = tid & 31, wid = tid >> 5;
    const int wm = (wid >> 2) * 64;
    const int wn = (wid & 3) * 32;
    const int m0 = blockIdx.y * BM;
    const int n0 = blockIdx.x * BN;
    const int KC = Kdim >> 5;

    float c[4][4][4];
#pragma unroll
    for (int i = 0; i < 4; i++)
#pragma unroll
        for (int j = 0; j < 4; j++)
#pragma unroll
            for (int q = 0; q < 4; q++) c[i][j][q] = 0.0f;

    const int lr = tid >> 2;
    const int lq = (tid & 3) * 8;

    auto load_stage = [&](int kc, int s) {
        const int k0 = kc << 5;
#pragma unroll
        for (int half = 0; half < 2; half++) {
            int r = lr + half * 64;
            CP_ASYNC16(sbA + (uint32_t)(s * STG_H + r * PKH + lq) * 2,
                       A + (size_t)(m0 + r) * Kdim + k0 + lq);
            CP_ASYNC16(sbB + (uint32_t)(s * STG_H + r * PKH + lq) * 2,
                       Wb + (size_t)(n0 + r) * Kdim + k0 + lq);
        }
    };

#pragma unroll
    for (int s = 0; s < NSTG - 1; s++) { load_stage(s, s); CP_COMMIT(); }

    for (int kc = 0; kc < KC; kc++) {
        const int s = kc % NSTG;
        CP_WAIT(NSTG - 2);
        __syncthreads();
        const int kl = kc + NSTG - 1;
        if (kl < KC) load_stage(kl, kl % NSTG);
        CP_COMMIT();

#pragma unroll
        for (int ks = 0; ks < 2; ks++) {
            uint32_t a[4][4];
#pragma unroll
            for (int mi = 0; mi < 4; mi++) {
                int row = wm + mi * 16 + (lane & 15);
                int col = ks * 16 + (lane >> 4) * 8;
                ldm_x4(a[mi][0], a[mi][1], a[mi][2], a[mi][3],
                       sbA + (uint32_t)(s * STG_H + row * PKH + col) * 2);
            }
            uint32_t b[4][2];
#pragma unroll
            for (int ni = 0; ni < 2; ni++) {
                int row = wn + ni * 16 + (lane & 7) + ((lane >> 4) << 3);
                int col = ks * 16 + ((lane >> 3) & 1) * 8;
                uint32_t r0, r1, r2, r3;
                ldm_x4(r0, r1, r2, r3, sbB + (uint32_t)(s * STG_H + row * PKH + col) * 2);
                b[ni * 2 + 0][0] = r0; b[ni * 2 + 0][1] = r1;
                b[ni * 2 + 1][0] = r2; b[ni * 2 + 1][1] = r3;
            }
#pragma unroll
            for (int mi = 0; mi < 4; mi++)
#pragma unroll
                for (int nj = 0; nj < 4; nj++)
                    mma_f16(c[mi][nj], a[mi], b[nj][0], b[nj][1]);
        }
    }

    const int gr = lane >> 2;
    const int gc = (lane & 3) * 2;
#pragma unroll
    for (int mi = 0; mi < 4; mi++) {
#pragma unroll
        for (int nj = 0; nj < 4; nj++) {
            int m = m0 + wm + mi * 16 + gr;
            int n = n0 + wn + nj * 8 + gc;
            float s0 = __ldg(&scales[n]);
            float s1 = __ldg(&scales[n + 1]);
            float2 v0 = {c[mi][nj][0] * s0, c[mi][nj][1] * s1};
            float2 v1 = {c[mi][nj][2] * s0, c[mi][nj][3] * s1};
            *(float2*)&out[(size_t)m * Ndim + n] = v0;
            *(float2*)&out[(size_t)(m + 8) * Ndim + n] = v1;
        }
    }
}

// ===================== conversions =====================
__global__ __launch_bounds__(256) void conv_w_kernel(const int* __restrict__ W,
                                                     __half* __restrict__ O, int n4)
{
    int i = blockIdx.x * blockDim.x + threadIdx.x;
    if (i >= n4) return;
    int4 w = ((const int4*)W)[i];
    __half o[4] = { __int2half_rn(w.x), __int2half_rn(w.y),
                    __int2half_rn(w.z), __int2half_rn(w.w) };
    ((uint2*)O)[i] = *(uint2*)o;
}

__global__ __launch_bounds__(256) void conv_x_kernel(const float* __restrict__ X,
                                                     __half* __restrict__ O, int n4)
{
    int i = blockIdx.x * blockDim.x + threadIdx.x;
    if (i >= n4) return;
    float4 v = ((const float4*)X)[i];
    __half o[4] = { __float2half_rn(v.x), __float2half_rn(v.y),
                    __float2half_rn(v.z), __float2half_rn(v.w) };
    ((uint2*)O)[i] = *(uint2*)o;
}

// ===================== split + L2 norm -> fp16 =====================
__global__ __launch_bounds__(256) void split_norm_kernel(
    const float* __restrict__ qkv, const float* __restrict__ gain_p,
    __half* __restrict__ q, __half* __restrict__ k, __half* __restrict__ v)
{
    int gw = (blockIdx.x * blockDim.x + threadIdx.x) >> 5;
    int lane = threadIdx.x & 31;
    int which = gw / (BB * TT * NHH);
    int rem = gw % (BB * TT * NHH);
    int b = rem / (TT * NHH);
    int rem2 = rem % (TT * NHH);
    int t = rem2 / NHH;
    int h = rem2 % NHH;

    const float* src = qkv + (size_t)(b * TT + t) * THREEC + which * CC + h * HDD + lane * 4;
    float4 x = *(const float4*)src;

    if (which != 2) {
        float ss = x.x * x.x + x.y * x.y + x.z * x.z + x.w * x.w;
#pragma unroll
        for (int o = 16; o > 0; o >>= 1) ss += __shfl_xor_sync(0xffffffffu, ss, o);
        float n = sqrtf(ss);
        float s = gain_p[0] / fmaxf(n, 1e-12f);
        x.x *= s; x.y *= s; x.z *= s; x.w *= s;
    }

    __half* dst = (which == 0) ? q : (which == 1) ? k : v;
    size_t base = ((size_t)(b * NHH + h) * TT + t) * HDD + lane * 4;
    __half o[4] = { __float2half_rn(x.x), __float2half_rn(x.y),
                    __float2half_rn(x.z), __float2half_rn(x.w) };
    *(uint2*)&dst[base] = *(uint2*)o;
}

// ===================== fp16 HMMA flash attention =====================
// 256 threads, 8 warps x 16 q-rows => BM=128 q-rows per CTA.
// K/V tiles (64 keys) double-buffered via cp.async.
#define FPH 136
#define FQ_H 0                       // Q: 128 rows
#define KV_H(s) (128 * FPH + (s) * 128 * FPH)      // stage s: K 64 rows then V 64 rows
#define FLASH_SMEM ((128 + 2 * 128) * FPH * 2)     // 104448 bytes

__global__ __launch_bounds__(256, 2) void flash_mma_kernel(
    const __half* __restrict__ Qg, const __half* __restrict__ Kg,
    const __half* __restrict__ Vg, __half* __restrict__ Yh)
{
    extern __shared__ __half fsm[];
    const uint32_t sb = smem_u32(fsm);
    const int tid = threadIdx.x, lane = tid & 31, wid = tid >> 5;
    const int wr = wid * 16;                       // warp's first q-row (0..112)
    const int qb = gridDim.x - 1 - blockIdx.x;     // heavy blocks first
    const int bh = blockIdx.y;
    const int q0 = qb * 128;
    const float SCLOG2E = 0.08838834764831845f * 1.4426950408889634f;

    const size_t bhoff = (size_t)bh * TT * HDD;
    const __half* Qb = Qg + bhoff;
    const __half* Kb = Kg + bhoff;
    const __half* Vb = Vg + bhoff;

    // ---- load Q tile (128 x 128) : plain loads, covered by first sync
    {
        const int row = tid >> 1;                 // 0..127
        const int c = (tid & 1) * 64;
#pragma unroll
        for (int q8 = 0; q8 < 64; q8 += 8) {
            uint4 qv = *(const uint4*)(Qb + (size_t)(q0 + row) * HDD + c + q8);
            uint32_t so = (row * FPH + c + q8) * 2;
            *(uint2*)((char*)fsm + so)     = make_uint2(qv.x, qv.y);
            *(uint2*)((char*)fsm + so + 8) = make_uint2(qv.z, qv.w);
        }
    }

    // cp.async K/V stage loader: 64 rows x 128 halves each, 256 threads
    const int krow = tid >> 2;                    // 0..63
    const int kcol = (tid & 3) * 32;              // halves
    auto load_kv = [&](int jb, int s) {
        const int k0 = jb * 64;
        const uint32_t kb_off = sb + KV_H(s) * 2;
        const uint32_t vb_off = kb_off + 64 * FPH * 2;
#pragma unroll
        for (int q8 = 0; q8 < 32; q8 += 8) {
            uint32_t so = (krow * FPH + kcol + q8) * 2;
            CP_ASYNC16(kb_off + so, Kb + (size_t)(k0 + krow) * HDD + kcol + q8);
            CP_ASYNC16(vb_off + so, Vb + (size_t)(k0 + krow) * HDD + kcol + q8);
        }
    };

    float o[16][4];
#pragma unroll
    for (int i = 0; i < 16; i++)
#pragma unroll
        for (int j = 0; j < 4; j++) o[i][j] = 0.0f;
    float m0v = -1e30f, m1v = -1e30f, l0 = 0.0f, l1 = 0.0f;

    const int jbmax = 2 * qb + 1;
    load_kv(0, 0);
    CP_COMMIT();

    for (int jb = 0; jb <= jbmax; jb++) {
        const int s_buf = jb & 1;
        __syncthreads();                          // prior compute done; Q visible on first iter
        if (jb + 1 <= jbmax) load_kv(jb + 1, (jb + 1) & 1);
        CP_COMMIT();
        CP_WAIT(1);                               // current stage's group complete
        __syncthreads();

        const uint32_t kbase = sb + KV_H(s_buf) * 2;
        const uint32_t vbase = kbase + 64 * FPH * 2;
        const int k0g = jb * 64;

        // ---- S = Q K^T
        float s[8][4];
#pragma unroll
        for (int i = 0; i < 8; i++)
#pragma unroll
            for (int j = 0; j < 4; j++) s[i][j] = 0.0f;

#pragma unroll
        for (int ks = 0; ks < 8; ks++) {
            uint32_t a[4];
            uint32_t qoff = sb + (uint32_t)((wr + (lane & 15)) * FPH + ks * 16 + (lane >> 4) * 8) * 2;
            ldm_x4(a[0], a[1], a[2], a[3], qoff);
#pragma unroll
            for (int nt2 = 0; nt2 < 4; nt2++) {
                uint32_t koff = kbase + (uint32_t)((nt2 * 16 + (lane & 7) + ((lane >> 4) << 3)) * FPH
                                                   + ks * 16 + ((lane >> 3) & 1) * 8) * 2;
                uint32_t b0, b1, b2, b3;
                ldm_x4(b0, b1, b2, b3, koff);
                mma_f16(s[nt2 * 2 + 0], a, b0, b1);
                mma_f16(s[nt2 * 2 + 1], a, b2, b3);
            }
        }

        // ---- scale (log2 domain) + causal mask (global indices)
        const int lr0 = wr + (lane >> 2);          // local q row (0..127)
        const int lc0 = (lane & 3) * 2;
#pragma unroll
        for (int nt = 0; nt < 8; nt++) {
#pragma unroll
            for (int j = 0; j < 4; j++) s[nt][j] *= SCLOG2E;
            if (jb >= 2 * qb) {
                int colg = k0g + nt * 8 + lc0;
                int rg0 = q0 + lr0;
                int rg1 = rg0 + 8;
                if (colg > rg0)     s[nt][0] = -1e30f;
                if (colg + 1 > rg0) s[nt][1] = -1e30f;
                if (colg > rg1)     s[nt][2] = -1e30f;
                if (colg + 1 > rg1) s[nt][3] = -1e30f;
            }
        }

        // ---- online softmax (base-2, f16x2 ex2)
        float rm0 = -1e30f, rm1 = -1e30f;
#pragma unroll
        for (int nt = 0; nt < 8; nt++) {
            rm0 = fmaxf(rm0, fmaxf(s[nt][0], s[nt][1]));
            rm1 = fmaxf(rm1, fmaxf(s[nt][2], s[nt][3]));
        }
        rm0 = fmaxf(rm0, __shfl_xor_sync(0xffffffffu, rm0, 1));
        rm0 = fmaxf(rm0, __shfl_xor_sync(0xffffffffu, rm0, 2));
        rm1 = fmaxf(rm1, __shfl_xor_sync(0xffffffffu, rm1, 1));
        rm1 = fmaxf(rm1, __shfl_xor_sync(0xffffffffu, rm1, 2));
        float mn0 = fmaxf(m0v, rm0), mn1 = fmaxf(m1v, rm1);
        float cor0 = exp2f(m0v - mn0), cor1 = exp2f(m1v - mn1);
        float sum0 = 0.0f, sum1 = 0.0f;
        uint32_t pf[4][4];
#pragma unroll
        for (int nt = 0; nt < 8; nt++) {
            __half2 z01 = __floats2half2_rn(s[nt][0] - mn0, s[nt][1] - mn0);
            __half2 z23 = __floats2half2_rn(s[nt][2] - mn1, s[nt][3] - mn1);
            uint32_t p01 = ex2_f16x2(*(uint32_t*)&z01);
            uint32_t p23 = ex2_f16x2(*(uint32_t*)&z23);
            float2 f01 = __half22float2(*(__half2*)&p01);
            float2 f23 = __half22float2(*(__half2*)&p23);
            sum0 += f01.x + f01.y;
            sum1 += f23.x + f23.y;
            int ks = nt >> 1;
            int hi2 = nt & 1;
            pf[ks][hi2 * 2 + 0] = p01;
            pf[ks][hi2 * 2 + 1] = p23;
        }
        sum0 += __shfl_xor_sync(0xffffffffu, sum0, 1);
        sum0 += __shfl_xor_sync(0xffffffffu, sum0, 2);
        sum1 += __shfl_xor_sync(0xffffffffu, sum1, 1);
        sum1 += __shfl_xor_sync(0xffffffffu, sum1, 2);
        l0 = l0 * cor0 + sum0;
        l1 = l1 * cor1 + sum1;
        m0v = mn0; m1v = mn1;
#pragma unroll
        for (int nt = 0; nt < 16; nt++) {
            o[nt][0] *= cor0; o[nt][1] *= cor0;
            o[nt][2] *= cor1; o[nt][3] *= cor1;
        }

        // ---- O += P V
#pragma unroll
        for (int ks = 0; ks < 4; ks++) {
#pragma unroll
            for (int nt2 = 0; nt2 < 8; nt2++) {
                uint32_t voff = vbase +
                    (uint32_t)((ks * 16 + (lane & 15)) * FPH + nt2 * 16 + (lane >> 4) * 8) * 2;
                uint32_t b0, b1, b2, b3;
                ldm_x4_t(b0, b1, b2, b3, voff);
                mma_f16(o[nt2 * 2 + 0], pf[ks], b0, b1);
                mma_f16(o[nt2 * 2 + 1], pf[ks], b2, b3);
            }
        }
    }

    // ---- epilogue
    const int b = bh / NHH, h = bh % NHH;
    const int r0 = wr + (lane >> 2);
    const int cbase = (lane & 3) * 2;
    float inv0 = 1.0f / l0, inv1 = 1.0f / l1;
    size_t rowA = (size_t)(b * TT + q0 + r0) * CC + h * HDD;
    size_t rowB = (size_t)(b * TT + q0 + r0 + 8) * CC + h * HDD;
#pragma unroll
    for (int nt = 0; nt < 16; nt++) {
        int col = nt * 8 + cbase;
        __half2 vA = {__float2half_rn(o[nt][0] * inv0), __float2half_rn(o[nt][1] * inv0)};
        __half2 vB = {__float2half_rn(o[nt][2] * inv1), __float2half_rn(o[nt][3] * inv1)};
        *(uint32_t*)&Yh[rowA + col] = *(uint32_t*)&vA;
        *(uint32_t*)&Yh[rowB + col] = *(uint32_t*)&vB;
    }
}

// ===================== launch =====================
extern "C" void kernel_launch(void* const* d_in, const int* in_sizes, int n_in,
                              void* d_out, int out_size)
{
    const float* x           = (const float*)d_in[0];
    const int*   attn_w      = (const int*)d_in[1];
    const float* attn_scales = (const float*)d_in[2];
    const int*   proj_w      = (const int*)d_in[3];
    const float* proj_scales = (const float*)d_in[4];
    const float* qk_gain     = (const float*)d_in[5];
    float* out = (float*)d_out;

    float* p_qkv;
    __half *p_wha, *p_whp, *p_xh, *p_qh, *p_kh, *p_vh, *p_yh;
    cudaGetSymbolAddress((void**)&p_qkv, g_qkv);
    cudaGetSymbolAddress((void**)&p_wha, g_wha);
    cudaGetSymbolAddress((void**)&p_whp, g_whp);
    cudaGetSymbolAddress((void**)&p_xh,  g_xh);
    cudaGetSymbolAddress((void**)&p_qh,  g_qh);
    cudaGetSymbolAddress((void**)&p_kh,  g_kh);
    cudaGetSymbolAddress((void**)&p_vh,  g_vh);
    cudaGetSymbolAddress((void**)&p_yh,  g_yh);

    cudaFuncSetAttribute(gemm_mma_f16, cudaFuncAttributeMaxDynamicSharedMemorySize, GEMM_SMEM);
    cudaFuncSetAttribute(flash_mma_kernel, cudaFuncAttributeMaxDynamicSharedMemorySize, FLASH_SMEM);

    // 0) weight conversions (int32 -> fp16, exact)
    conv_w_kernel<<<(THREEC * CC / 4 + 255) / 256, 256>>>(attn_w, p_wha, THREEC * CC / 4);
    conv_w_kernel<<<(CC * CC / 4 + 255) / 256, 256>>>(proj_w, p_whp, CC * CC / 4);

    // 1) x -> fp16
    conv_x_kernel<<<(MTOK * CC / 4 + 255) / 256, 256>>>(x, p_xh, MTOK * CC / 4);

    // 2) QKV = x @ Wa^T
    gemm_mma_f16<<<dim3(THREEC / BN, MTOK / BM), 256, GEMM_SMEM>>>(
        p_xh, p_wha, attn_scales, p_qkv, THREEC, CC);

    // 3) split + L2 norm -> fp16 q/k/v
    split_norm_kernel<<<3 * BB * TT * NHH / 8, 256>>>(p_qkv, qk_gain, p_qh, p_kh, p_vh);

    // 4) fp16 HMMA flash attention (BM=128, cp.async double-buffer)
    flash_mma_kernel<<<dim3(TT / 128, BB * NHH), 256, FLASH_SMEM>>>(p_qh, p_kh, p_vh, p_yh);

    // 5) out = y @ Wp^T
    gemm_mma_f16<<<dim3(CC / BN, MTOK / BM), 256, GEMM_SMEM>>>(
        p_yh, p_whp, proj_scales, out, CC, CC);
}

// round 16
// speedup vs baseline: 1.5328x; 1.1000x over previous
#include <cuda_runtime.h>
#include <cuda_fp16.h>
#include <stdint.h>
#include <math.h>

// Problem constants
#define BB 2
#define TT 2048
#define CC 2048
#define NHH 16
#define HDD 128
#define MTOK (BB*TT)        // 4096
#define THREEC (3*CC)       // 6144

// ---------------- scratch (device globals) ----------------
__device__ float  g_qkv[(size_t)MTOK * THREEC];
__device__ __half g_wha[(size_t)THREEC * CC];
__device__ __half g_whp[(size_t)CC * CC];
__device__ __half g_xh[(size_t)MTOK * CC];
__device__ __half g_qh[(size_t)BB*NHH*TT*HDD];
__device__ __half g_kh[(size_t)BB*NHH*TT*HDD];
__device__ __half g_vh[(size_t)BB*NHH*TT*HDD];
__device__ __half g_yh[(size_t)MTOK * CC];

// ===================== helpers =====================
__device__ __forceinline__ uint32_t smem_u32(const void* p) {
    uint32_t a;
    asm("{ .reg .u64 t; cvta.to.shared.u64 t, %1; cvt.u32.u64 %0, t; }" : "=r"(a) : "l"(p));
    return a;
}
#define CP_ASYNC16(s, g) asm volatile("cp.async.cg.shared.global [%0], [%1], 16;" :: "r"(s), "l"(g))
#define CP_COMMIT()      asm volatile("cp.async.commit_group;" ::: "memory")
#define CP_WAIT(n)       asm volatile("cp.async.wait_group %0;" :: "n"(n) : "memory")

__device__ __forceinline__ void ldm_x4(uint32_t& r0, uint32_t& r1, uint32_t& r2, uint32_t& r3,
                                       uint32_t addr) {
    asm volatile("ldmatrix.sync.aligned.m8n8.x4.shared.b16 {%0,%1,%2,%3}, [%4];"
                 : "=r"(r0), "=r"(r1), "=r"(r2), "=r"(r3) : "r"(addr));
}
__device__ __forceinline__ void ldm_x4_t(uint32_t& r0, uint32_t& r1, uint32_t& r2, uint32_t& r3,
                                         uint32_t addr) {
    asm volatile("ldmatrix.sync.aligned.m8n8.x4.trans.shared.b16 {%0,%1,%2,%3}, [%4];"
                 : "=r"(r0), "=r"(r1), "=r"(r2), "=r"(r3) : "r"(addr));
}
__device__ __forceinline__ void mma_f16(float* c, const uint32_t* a, uint32_t b0, uint32_t b1) {
    asm volatile(
        "mma.sync.aligned.m16n8k16.row.col.f32.f16.f16.f32 "
        "{%0,%1,%2,%3}, {%4,%5,%6,%7}, {%8,%9}, {%0,%1,%2,%3};"
        : "+f"(c[0]), "+f"(c[1]), "+f"(c[2]), "+f"(c[3])
        : "r"(a[0]), "r"(a[1]), "r"(a[2]), "r"(a[3]), "r"(b0), "r"(b1));
}
__device__ __forceinline__ uint32_t ex2_f16x2(uint32_t z) {
    uint32_t r;
    asm volatile("ex2.approx.f16x2 %0, %1;" : "=r"(r) : "r"(z));
    return r;
}

// ===================== fp16 HMMA weight GEMM =====================
// out[m,n] = scales[n] * sum_k A[m,k] * W[n,k]
// 128x128x32 CTA tile, 512 threads = 16 warps of 32x32, 4-stage cp.async.
#define BM 128
#define BN 128
#define PKH 40                        // halves pitch
#define STG_H (BM * PKH)              // 5120 halves
#define NSTG 4
#define GEMM_SMEM (NSTG * STG_H * 2 * 2)   // 81920 bytes

__global__ __launch_bounds__(512, 2) void gemm_mma_f16(
    const __half* __restrict__ A, const __half* __restrict__ Wb,
    const float* __restrict__ scales, float* __restrict__ out, int Ndim, int Kdim)
{
    extern __shared__ __half smg[];
    const uint32_t sbA = smem_u32(smg);
    const uint32_t sbB = sbA + NSTG * STG_H * 2;

    const int tid = threadIdx.x, lane = tid & 31, wid = tid >> 5;
    const int wm = (wid >> 2) * 32;    // 4 warp-rows x 32
    const int wn = (wid & 3) * 32;     // 4 warp-cols x 32
    const int m0 = blockIdx.y * BM;
    const int n0 = blockIdx.x * BN;
    const int KC = Kdim >> 5;

    float c[2][4][4];
#pragma unroll
    for (int i = 0; i < 2; i++)
#pragma unroll
        for (int j = 0; j < 4; j++)
#pragma unroll
            for (int q = 0; q < 4; q++) c[i][j][q] = 0.0f;

    // one 16B cp.async per thread per matrix per stage
    const int lr = tid >> 2;           // 0..127
    const int lq = (tid & 3) * 8;      // halves 0,8,16,24

    auto load_stage = [&](int kc, int s) {
        const int k0 = kc << 5;
        CP_ASYNC16(sbA + (uint32_t)(s * STG_H + lr * PKH + lq) * 2,
                   A + (size_t)(m0 + lr) * Kdim + k0 + lq);
        CP_ASYNC16(sbB + (uint32_t)(s * STG_H + lr * PKH + lq) * 2,
                   Wb + (size_t)(n0 + lr) * Kdim + k0 + lq);
    };

#pragma unroll
    for (int s = 0; s < NSTG - 1; s++) { load_stage(s, s); CP_COMMIT(); }

    for (int kc = 0; kc < KC; kc++) {
        const int s = kc % NSTG;
        CP_WAIT(NSTG - 2);
        __syncthreads();
        const int kl = kc + NSTG - 1;
        if (kl < KC) load_stage(kl, kl % NSTG);
        CP_COMMIT();

#pragma unroll
        for (int ks = 0; ks < 2; ks++) {
            uint32_t a[2][4];
#pragma unroll
            for (int mi = 0; mi < 2; mi++) {
                int row = wm + mi * 16 + (lane & 15);
                int col = ks * 16 + (lane >> 4) * 8;
                ldm_x4(a[mi][0], a[mi][1], a[mi][2], a[mi][3],
                       sbA + (uint32_t)(s * STG_H + row * PKH + col) * 2);
            }
            uint32_t b[4][2];
#pragma unroll
            for (int ni = 0; ni < 2; ni++) {
                int row = wn + ni * 16 + (lane & 7) + ((lane >> 4) << 3);
                int col = ks * 16 + ((lane >> 3) & 1) * 8;
                uint32_t r0, r1, r2, r3;
                ldm_x4(r0, r1, r2, r3, sbB + (uint32_t)(s * STG_H + row * PKH + col) * 2);
                b[ni * 2 + 0][0] = r0; b[ni * 2 + 0][1] = r1;
                b[ni * 2 + 1][0] = r2; b[ni * 2 + 1][1] = r3;
            }
#pragma unroll
            for (int mi = 0; mi < 2; mi++)
#pragma unroll
                for (int nj = 0; nj < 4; nj++)
                    mma_f16(c[mi][nj], a[mi], b[nj][0], b[nj][1]);
        }
    }

    const int gr = lane >> 2;
    const int gc = (lane & 3) * 2;
#pragma unroll
    for (int mi = 0; mi < 2; mi++) {
#pragma unroll
        for (int nj = 0; nj < 4; nj++) {
            int m = m0 + wm + mi * 16 + gr;
            int n = n0 + wn + nj * 8 + gc;
            float s0 = __ldg(&scales[n]);
            float s1 = __ldg(&scales[n + 1]);
            float2 v0 = {c[mi][nj][0] * s0, c[mi][nj][1] * s1};
            float2 v1 = {c[mi][nj][2] * s0, c[mi][nj][3] * s1};
            *(float2*)&out[(size_t)m * Ndim + n] = v0;
            *(float2*)&out[(size_t)(m + 8) * Ndim + n] = v1;
        }
    }
}

// ===================== conversions =====================
__global__ __launch_bounds__(256) void conv_w_kernel(const int* __restrict__ W,
                                                     __half* __restrict__ O, int n4)
{
    int i = blockIdx.x * blockDim.x + threadIdx.x;
    if (i >= n4) return;
    int4 w = ((const int4*)W)[i];
    __half o[4] = { __int2half_rn(w.x), __int2half_rn(w.y),
                    __int2half_rn(w.z), __int2half_rn(w.w) };
    ((uint2*)O)[i] = *(uint2*)o;
}

__global__ __launch_bounds__(256) void conv_x_kernel(const float* __restrict__ X,
                                                     __half* __restrict__ O, int n4)
{
    int i = blockIdx.x * blockDim.x + threadIdx.x;
    if (i >= n4) return;
    float4 v = ((const float4*)X)[i];
    __half o[4] = { __float2half_rn(v.x), __float2half_rn(v.y),
                    __float2half_rn(v.z), __float2half_rn(v.w) };
    ((uint2*)O)[i] = *(uint2*)o;
}

// ===================== split + L2 norm -> fp16 =====================
__global__ __launch_bounds__(256) void split_norm_kernel(
    const float* __restrict__ qkv, const float* __restrict__ gain_p,
    __half* __restrict__ q, __half* __restrict__ k, __half* __restrict__ v)
{
    int gw = (blockIdx.x * blockDim.x + threadIdx.x) >> 5;
    int lane = threadIdx.x & 31;
    int which = gw / (BB * TT * NHH);
    int rem = gw % (BB * TT * NHH);
    int b = rem / (TT * NHH);
    int rem2 = rem % (TT * NHH);
    int t = rem2 / NHH;
    int h = rem2 % NHH;

    const float* src = qkv + (size_t)(b * TT + t) * THREEC + which * CC + h * HDD + lane * 4;
    float4 x = *(const float4*)src;

    if (which != 2) {
        float ss = x.x * x.x + x.y * x.y + x.z * x.z + x.w * x.w;
#pragma unroll
        for (int o = 16; o > 0; o >>= 1) ss += __shfl_xor_sync(0xffffffffu, ss, o);
        float n = sqrtf(ss);
        float s = gain_p[0] / fmaxf(n, 1e-12f);
        x.x *= s; x.y *= s; x.z *= s; x.w *= s;
    }

    __half* dst = (which == 0) ? q : (which == 1) ? k : v;
    size_t base = ((size_t)(b * NHH + h) * TT + t) * HDD + lane * 4;
    __half o[4] = { __float2half_rn(x.x), __float2half_rn(x.y),
                    __float2half_rn(x.z), __float2half_rn(x.w) };
    *(uint2*)&dst[base] = *(uint2*)o;
}

// ===================== fp16 HMMA flash attention =====================
// 256 threads, 8 warps x 16 q-rows => BM=128 q-rows per CTA.
// K/V tiles (64 keys) double-buffered via cp.async.
#define FPH 136
#define KV_H(s) (128 * FPH + (s) * 128 * FPH)      // stage s: K 64 rows then V 64 rows
#define FLASH_SMEM ((128 + 2 * 128) * FPH * 2)     // 104448 bytes

__global__ __launch_bounds__(256, 2) void flash_mma_kernel(
    const __half* __restrict__ Qg, const __half* __restrict__ Kg,
    const __half* __restrict__ Vg, __half* __restrict__ Yh)
{
    extern __shared__ __half fsm[];
    const uint32_t sb = smem_u32(fsm);
    const int tid = threadIdx.x, lane = tid & 31, wid = tid >> 5;
    const int wr = wid * 16;
    const int qb = gridDim.x - 1 - blockIdx.x;     // heavy blocks first
    const int bh = blockIdx.y;
    const int q0 = qb * 128;
    const float SCLOG2E = 0.08838834764831845f * 1.4426950408889634f;

    const size_t bhoff = (size_t)bh * TT * HDD;
    const __half* Qb = Qg + bhoff;
    const __half* Kb = Kg + bhoff;
    const __half* Vb = Vg + bhoff;

    {
        const int row = tid >> 1;
        const int c = (tid & 1) * 64;
#pragma unroll
        for (int q8 = 0; q8 < 64; q8 += 8) {
            uint4 qv = *(const uint4*)(Qb + (size_t)(q0 + row) * HDD + c + q8);
            uint32_t so = (row * FPH + c + q8) * 2;
            *(uint2*)((char*)fsm + so)     = make_uint2(qv.x, qv.y);
            *(uint2*)((char*)fsm + so + 8) = make_uint2(qv.z, qv.w);
        }
    }

    const int krow = tid >> 2;
    const int kcol = (tid & 3) * 32;
    auto load_kv = [&](int jb, int s) {
        const int k0 = jb * 64;
        const uint32_t kb_off = sb + KV_H(s) * 2;
        const uint32_t vb_off = kb_off + 64 * FPH * 2;
#pragma unroll
        for (int q8 = 0; q8 < 32; q8 += 8) {
            uint32_t so = (krow * FPH + kcol + q8) * 2;
            CP_ASYNC16(kb_off + so, Kb + (size_t)(k0 + krow) * HDD + kcol + q8);
            CP_ASYNC16(vb_off + so, Vb + (size_t)(k0 + krow) * HDD + kcol + q8);
        }
    };

    float o[16][4];
#pragma unroll
    for (int i = 0; i < 16; i++)
#pragma unroll
        for (int j = 0; j < 4; j++) o[i][j] = 0.0f;
    float m0v = -1e30f, m1v = -1e30f, l0 = 0.0f, l1 = 0.0f;

    const int jbmax = 2 * qb + 1;
    load_kv(0, 0);
    CP_COMMIT();

    for (int jb = 0; jb <= jbmax; jb++) {
        const int s_buf = jb & 1;
        __syncthreads();
        if (jb + 1 <= jbmax) load_kv(jb + 1, (jb + 1) & 1);
        CP_COMMIT();
        CP_WAIT(1);
        __syncthreads();

        const uint32_t kbase = sb + KV_H(s_buf) * 2;
        const uint32_t vbase = kbase + 64 * FPH * 2;
        const int k0g = jb * 64;

        float s[8][4];
#pragma unroll
        for (int i = 0; i < 8; i++)
#pragma unroll
            for (int j = 0; j < 4; j++) s[i][j] = 0.0f;

#pragma unroll
        for (int ks = 0; ks < 8; ks++) {
            uint32_t a[4];
            uint32_t qoff = sb + (uint32_t)((wr + (lane & 15)) * FPH + ks * 16 + (lane >> 4) * 8) * 2;
            ldm_x4(a[0], a[1], a[2], a[3], qoff);
#pragma unroll
            for (int nt2 = 0; nt2 < 4; nt2++) {
                uint32_t koff = kbase + (uint32_t)((nt2 * 16 + (lane & 7) + ((lane >> 4) << 3)) * FPH
                                                   + ks * 16 + ((lane >> 3) & 1) * 8) * 2;
                uint32_t b0, b1, b2, b3;
                ldm_x4(b0, b1, b2, b3, koff);
                mma_f16(s[nt2 * 2 + 0], a, b0, b1);
                mma_f16(s[nt2 * 2 + 1], a, b2, b3);
            }
        }

        const int lr0 = wr + (lane >> 2);
        const int lc0 = (lane & 3) * 2;
#pragma unroll
        for (int nt = 0; nt < 8; nt++) {
#pragma unroll
            for (int j = 0; j < 4; j++) s[nt][j] *= SCLOG2E;
            if (jb >= 2 * qb) {
                int colg = k0g + nt * 8 + lc0;
                int rg0 = q0 + lr0;
                int rg1 = rg0 + 8;
                if (colg > rg0)     s[nt][0] = -1e30f;
                if (colg + 1 > rg0) s[nt][1] = -1e30f;
                if (colg > rg1)     s[nt][2] = -1e30f;
                if (colg + 1 > rg1) s[nt][3] = -1e30f;
            }
        }

        float rm0 = -1e30f, rm1 = -1e30f;
#pragma unroll
        for (int nt = 0; nt < 8; nt++) {
            rm0 = fmaxf(rm0, fmaxf(s[nt][0], s[nt][1]));
            rm1 = fmaxf(rm1, fmaxf(s[nt][2], s[nt][3]));
        }
        rm0 = fmaxf(rm0, __shfl_xor_sync(0xffffffffu, rm0, 1));
        rm0 = fmaxf(rm0, __shfl_xor_sync(0xffffffffu, rm0, 2));
        rm1 = fmaxf(rm1, __shfl_xor_sync(0xffffffffu, rm1, 1));
        rm1 = fmaxf(rm1, __shfl_xor_sync(0xffffffffu, rm1, 2));
        float mn0 = fmaxf(m0v, rm0), mn1 = fmaxf(m1v, rm1);
        float cor0 = exp2f(m0v - mn0), cor1 = exp2f(m1v - mn1);
        float sum0 = 0.0f, sum1 = 0.0f;
        uint32_t pf[4][4];
#pragma unroll
        for (int nt = 0; nt < 8; nt++) {
            __half2 z01 = __floats2half2_rn(s[nt][0] - mn0, s[nt][1] - mn0);
            __half2 z23 = __floats2half2_rn(s[nt][2] - mn1, s[nt][3] - mn1);
            uint32_t p01 = ex2_f16x2(*(uint32_t*)&z01);
            uint32_t p23 = ex2_f16x2(*(uint32_t*)&z23);
            float2 f01 = __half22float2(*(__half2*)&p01);
            float2 f23 = __half22float2(*(__half2*)&p23);
            sum0 += f01.x + f01.y;
            sum1 += f23.x + f23.y;
            int ks = nt >> 1;
            int hi2 = nt & 1;
            pf[ks][hi2 * 2 + 0] = p01;
            pf[ks][hi2 * 2 + 1] = p23;
        }
        sum0 += __shfl_xor_sync(0xffffffffu, sum0, 1);
        sum0 += __shfl_xor_sync(0xffffffffu, sum0, 2);
        sum1 += __shfl_xor_sync(0xffffffffu, sum1, 1);
        sum1 += __shfl_xor_sync(0xffffffffu, sum1, 2);
        l0 = l0 * cor0 + sum0;
        l1 = l1 * cor1 + sum1;
        m0v = mn0; m1v = mn1;
#pragma unroll
        for (int nt = 0; nt < 16; nt++) {
            o[nt][0] *= cor0; o[nt][1] *= cor0;
            o[nt][2] *= cor1; o[nt][3] *= cor1;
        }

#pragma unroll
        for (int ks = 0; ks < 4; ks++) {
#pragma unroll
            for (int nt2 = 0; nt2 < 8; nt2++) {
                uint32_t voff = vbase +
                    (uint32_t)((ks * 16 + (lane & 15)) * FPH + nt2 * 16 + (lane >> 4) * 8) * 2;
                uint32_t b0, b1, b2, b3;
                ldm_x4_t(b0, b1, b2, b3, voff);
                mma_f16(o[nt2 * 2 + 0], pf[ks], b0, b1);
                mma_f16(o[nt2 * 2 + 1], pf[ks], b2, b3);
            }
        }
    }

    const int b = bh / NHH, h = bh % NHH;
    const int r0 = wr + (lane >> 2);
    const int cbase = (lane & 3) * 2;
    float inv0 = 1.0f / l0, inv1 = 1.0f / l1;
    size_t rowA = (size_t)(b * TT + q0 + r0) * CC + h * HDD;
    size_t rowB = (size_t)(b * TT + q0 + r0 + 8) * CC + h * HDD;
#pragma unroll
    for (int nt = 0; nt < 16; nt++) {
        int col = nt * 8 + cbase;
        __half2 vA = {__float2half_rn(o[nt][0] * inv0), __float2half_rn(o[nt][1] * inv0)};
        __half2 vB = {__float2half_rn(o[nt][2] * inv1), __float2half_rn(o[nt][3] * inv1)};
        *(uint32_t*)&Yh[rowA + col] = *(uint32_t*)&vA;
        *(uint32_t*)&Yh[rowB + col] = *(uint32_t*)&vB;
    }
}

// ===================== launch =====================
extern "C" void kernel_launch(void* const* d_in, const int* in_sizes, int n_in,
                              void* d_out, int out_size)
{
    const float* x           = (const float*)d_in[0];
    const int*   attn_w      = (const int*)d_in[1];
    const float* attn_scales = (const float*)d_in[2];
    const int*   proj_w      = (const int*)d_in[3];
    const float* proj_scales = (const float*)d_in[4];
    const float* qk_gain     = (const float*)d_in[5];
    float* out = (float*)d_out;

    float* p_qkv;
    __half *p_wha, *p_whp, *p_xh, *p_qh, *p_kh, *p_vh, *p_yh;
    cudaGetSymbolAddress((void**)&p_qkv, g_qkv);
    cudaGetSymbolAddress((void**)&p_wha, g_wha);
    cudaGetSymbolAddress((void**)&p_whp, g_whp);
    cudaGetSymbolAddress((void**)&p_xh,  g_xh);
    cudaGetSymbolAddress((void**)&p_qh,  g_qh);
    cudaGetSymbolAddress((void**)&p_kh,  g_kh);
    cudaGetSymbolAddress((void**)&p_vh,  g_vh);
    cudaGetSymbolAddress((void**)&p_yh,  g_yh);

    cudaFuncSetAttribute(gemm_mma_f16, cudaFuncAttributeMaxDynamicSharedMemorySize, GEMM_SMEM);
    cudaFuncSetAttribute(flash_mma_kernel, cudaFuncAttributeMaxDynamicSharedMemorySize, FLASH_SMEM);

    // 0) weight conversions (int32 -> fp16, exact)
    conv_w_kernel<<<(THREEC * CC / 4 + 255) / 256, 256>>>(attn_w, p_wha, THREEC * CC / 4);
    conv_w_kernel<<<(CC * CC / 4 + 255) / 256, 256>>>(proj_w, p_whp, CC * CC / 4);

    // 1) x -> fp16
    conv_x_kernel<<<(MTOK * CC / 4 + 255) / 256, 256>>>(x, p_xh, MTOK * CC / 4);

    // 2) QKV = x @ Wa^T
    gemm_mma_f16<<<dim3(THREEC / BN, MTOK / BM), 512, GEMM_SMEM>>>(
        p_xh, p_wha, attn_scales, p_qkv, THREEC, CC);

    // 3) split + L2 norm -> fp16 q/k/v
    split_norm_kernel<<<3 * BB * TT * NHH / 8, 256>>>(p_qkv, qk_gain, p_qh, p_kh, p_vh);

    // 4) fp16 HMMA flash attention (BM=128, cp.async double-buffer)
    flash_mma_kernel<<<dim3(TT / 128, BB * NHH), 256, FLASH_SMEM>>>(p_qh, p_kh, p_vh, p_yh);

    // 5) out = y @ Wp^T
    gemm_mma_f16<<<dim3(CC / BN, MTOK / BM), 512, GEMM_SMEM>>>(
        p_yh, p_whp, proj_scales, out, CC, CC);
}